// round 7
// baseline (speedup 1.0000x reference)
#include <cuda_runtime.h>
#include <cuda_fp16.h>
#include <cstdint>

#define NBATCH 4
#define NTOK   4096
#define DIM    512
#define MTOT   (NBATCH * NTOK)
#define SM_SCALE 0.044194173824159216f   // 1/sqrt(512)

// ---------------- scratch (half precision) ----------------
__device__ __half g_Q [(size_t)MTOT * DIM];            // 16 MB, cols perm16, pre-scaled
__device__ __half g_K [(size_t)MTOT * DIM];            // 16 MB, cols perm16
__device__ __half g_Vt[(size_t)MTOT * DIM];            // 16 MB, per-batch [dim][tok], tok perm16
__device__ __half g_S [(size_t)NBATCH * NTOK * NTOK];  // 134 MB (hosts prepped inputs pre-scores)
__device__ __half g_Wt[3ULL * DIM * DIM];              // 1.5 MB transposed + perm16

// ---------------- helpers ----------------
// perm16: logical index j in a 16-group -> storage position (frag pairs contiguous)
__device__ __forceinline__ int pos16(int j) {
    return ((j & 6) << 1) | ((j & 8) >> 2) | (j & 1);
}
__device__ __forceinline__ void mma_f16(float* d, const uint32_t* a, const uint32_t* b) {
    asm volatile(
        "mma.sync.aligned.m16n8k16.row.col.f32.f16.f16.f32 "
        "{%0,%1,%2,%3}, {%4,%5,%6,%7}, {%8,%9}, {%0,%1,%2,%3};"
        : "+f"(d[0]), "+f"(d[1]), "+f"(d[2]), "+f"(d[3])
        : "r"(a[0]), "r"(a[1]), "r"(a[2]), "r"(a[3]), "r"(b[0]), "r"(b[1]));
}
__device__ __forceinline__ uint32_t smem_u32(const void* p) {
    uint32_t r;
    asm("{ .reg .u64 t; cvta.to.shared.u64 t, %1; cvt.u32.u64 %0, t; }" : "=r"(r) : "l"(p));
    return r;
}
__device__ __forceinline__ void cpa16(uint32_t dst, const void* src) {
    asm volatile("cp.async.cg.shared.global [%0], [%1], 16;" :: "r"(dst), "l"(src));
}
#define CP_COMMIT() asm volatile("cp.async.commit_group;" ::: "memory")
#define CP_WAIT2()  asm volatile("cp.async.wait_group 2;" ::: "memory")

// ---------------- tiling ----------------
#define BM 128
#define BN 256
#define BK 64                          // halves per chunk (4 k16 steps)
#define ROWB 160                       // bytes/row: 128B data + 32B pad (word stride 40)
#define TILE_A (128 * ROWB)            // 20480 B
#define TILE_B (256 * ROWB)            // 40960 B
#define STAGE_BYTES (TILE_A + TILE_B)  // 61440 B
#define NSTAGE 3
#define SMEM_TOT (NSTAGE * STAGE_BYTES)   // 184320 B

// ---------------- fp16 tensor-core GEMM: C[M,N] = alpha*(A @ B^T + bias) ----------------
// A: [M x K] half row-major (lda), B: [N x K] half row-major (ldb), both perm16 in k-groups.
// 8 warps, warp tile 64x64 (2 x 4 warp grid over the 128x256 CTA tile).
// OM: 0 = fp32 plain; 1 = half, col perm16 (Q/K proj); 2 = half, col perm16 (scores);
//     3 = half transposed [dim][tok], tok perm16 (V proj).
template <bool BIAS, int OM>
__global__ __launch_bounds__(256, 1)
void gemm_h(const __half* __restrict__ Ag, const __half* __restrict__ Bg,
            const float* __restrict__ bias, void* __restrict__ Cg,
            int N, int K, int lda, int ldb, float alpha,
            long long sA, long long sB, long long sC) {
    extern __shared__ char smem[];
    const uint32_t sbase = smem_u32(smem);

    const int t    = threadIdx.x;
    const int lane = t & 31;
    const int w    = t >> 5;
    const int wm   = (w & 1) * 64;
    const int wn   = (w >> 1) * 64;
    const int m0   = blockIdx.y * BM;
    const int n0   = blockIdx.x * BN;
    const int bz   = blockIdx.z;

    const __half* A = Ag + (long long)bz * sA;
    const __half* B = Bg + (long long)bz * sB;

    // staging: 8 lanes per row (16B chunks), thread covers rows rb+32i (A) / rb+32i (B)
    const int rb = t >> 3;            // 0..31
    const int ch = t & 7;             // 0..7
    const __half* Arow = A + (long long)m0 * lda + ch * 8;
    const __half* Brow = B + (long long)n0 * ldb + ch * 8;

    auto issue = [&](int c, int buf) {
        const int k0 = c * BK;
        const uint32_t da = sbase + (uint32_t)buf * STAGE_BYTES;
        const uint32_t db = da + TILE_A;
#pragma unroll
        for (int i = 0; i < 4; i++) {
            const int r = rb + 32 * i;
            cpa16(da + r * ROWB + ch * 16, Arow + (long long)r * lda + k0);
        }
#pragma unroll
        for (int i = 0; i < 8; i++) {
            const int r = rb + 32 * i;
            cpa16(db + r * ROWB + ch * 16, Brow + (long long)r * ldb + k0);
        }
    };

    float acc[4][8][4];
#pragma unroll
    for (int i = 0; i < 4; i++)
#pragma unroll
        for (int j = 0; j < 8; j++)
#pragma unroll
            for (int q = 0; q < 4; q++) acc[i][j][q] = 0.0f;

    const int nchunk = K / BK;
    issue(0, 0); CP_COMMIT();
    issue(1, 1); CP_COMMIT();
    issue(2, 2); CP_COMMIT();

    const int fr = lane >> 2;
    const int fj = lane & 3;

    for (int c = 0; c < nchunk; c++) {
        const int buf = c % NSTAGE;
        CP_WAIT2();
        __syncthreads();

        const char* As = smem + buf * STAGE_BYTES;
        const char* Bs = As + TILE_A;

#pragma unroll
        for (int ks = 0; ks < 4; ks++) {
            const int off = ks * 32 + 8 * fj;
            uint32_t a[4][4], b[8][2];
#pragma unroll
            for (int ma = 0; ma < 4; ma++) {
                const char* pr = As + (wm + 16 * ma + fr) * ROWB + off;
                uint2 lo = *reinterpret_cast<const uint2*>(pr);
                uint2 hi = *reinterpret_cast<const uint2*>(pr + 8 * ROWB);
                a[ma][0] = lo.x; a[ma][2] = lo.y;
                a[ma][1] = hi.x; a[ma][3] = hi.y;
            }
#pragma unroll
            for (int na = 0; na < 8; na++) {
                uint2 v = *reinterpret_cast<const uint2*>(Bs + (wn + 8 * na + fr) * ROWB + off);
                b[na][0] = v.x; b[na][1] = v.y;
            }
#pragma unroll
            for (int ma = 0; ma < 4; ma++)
#pragma unroll
                for (int na = 0; na < 8; na++)
                    mma_f16(acc[ma][na], a[ma], b[na]);
        }

        __syncthreads();
        if (c + NSTAGE < nchunk) issue(c + NSTAGE, buf);
        CP_COMMIT();
    }

    // ---------------- epilogue ----------------
    const int fp = 2 * fj;
#pragma unroll
    for (int ma = 0; ma < 4; ma++) {
        const int r0 = m0 + wm + ma * 16 + fr;
#pragma unroll
        for (int na = 0; na < 8; na++) {
            const int col = n0 + wn + na * 8 + fp;   // logical col (even)
            float v0 = acc[ma][na][0], v1 = acc[ma][na][1];
            float v2 = acc[ma][na][2], v3 = acc[ma][na][3];
            if (BIAS) {
                const float b0 = bias[col], b1 = bias[col + 1];
                v0 += b0; v1 += b1; v2 += b0; v3 += b1;
            }
            v0 *= alpha; v1 *= alpha; v2 *= alpha; v3 *= alpha;

            if (OM == 3) {
                const int tokb = (r0 & (NTOK - 1)) & ~15;
                const int tp   = pos16(r0 & 15);
                __half* o = (__half*)Cg + (long long)(r0 >> 12) * ((long long)DIM * NTOK);
                o[(long long)col * NTOK + tokb + tp]           = __float2half_rn(v0);
                o[(long long)(col + 1) * NTOK + tokb + tp]     = __float2half_rn(v1);
                o[(long long)col * NTOK + tokb + tp + 2]       = __float2half_rn(v2);
                o[(long long)(col + 1) * NTOK + tokb + tp + 2] = __float2half_rn(v3);
            } else if (OM == 1 || OM == 2) {
                const int scol = (col & ~15) | pos16(col & 15);
                __half* o = (__half*)Cg + (long long)bz * sC;
                *reinterpret_cast<__half2*>(o + (long long)r0 * N + scol) =
                    __floats2half2_rn(v0, v1);
                *reinterpret_cast<__half2*>(o + (long long)(r0 + 8) * N + scol) =
                    __floats2half2_rn(v2, v3);
            } else {
                float* o = (float*)Cg + (long long)bz * sC;
                *reinterpret_cast<float2*>(o + (long long)r0 * N + col)       = make_float2(v0, v1);
                *reinterpret_cast<float2*>(o + (long long)(r0 + 8) * N + col) = make_float2(v2, v3);
            }
        }
    }
}

// ---------------- input prepass: fp32 -> half with perm16 ----------------
__global__ __launch_bounds__(256)
void prep_h(const float* __restrict__ in, __half* __restrict__ out, int n16) {
    int i = blockIdx.x * 256 + threadIdx.x;
    if (i >= n16) return;
    const float4* p = reinterpret_cast<const float4*>(in) + 4 * (size_t)i;
    float L[16];
    *reinterpret_cast<float4*>(L)      = p[0];
    *reinterpret_cast<float4*>(L + 4)  = p[1];
    *reinterpret_cast<float4*>(L + 8)  = p[2];
    *reinterpret_cast<float4*>(L + 12) = p[3];
    __half2 h[8];
#pragma unroll
    for (int tt = 0; tt < 4; tt++) {
        h[2 * tt]     = __floats2half2_rn(L[2 * tt],     L[2 * tt + 1]);
        h[2 * tt + 1] = __floats2half2_rn(L[2 * tt + 8], L[2 * tt + 9]);
    }
    uint4* o = reinterpret_cast<uint4*>(out + 16 * (size_t)i);
    o[0] = *reinterpret_cast<uint4*>(h);
    o[1] = *reinterpret_cast<uint4*>(h + 4);
}

// ---------------- 512x512 weight transpose -> half + perm16 on in_dim ----------------
__global__ void transpose512h(const float* __restrict__ in, __half* __restrict__ out) {
    __shared__ float tile[32][33];
    int x = blockIdx.x * 32 + threadIdx.x;
    int y0 = blockIdx.y * 32;
#pragma unroll
    for (int j = threadIdx.y; j < 32; j += 8)
        tile[j][threadIdx.x] = in[(size_t)(y0 + j) * 512 + x];
    __syncthreads();
    int ox = y0 + threadIdx.x;
    int sx = (ox & ~15) | pos16(ox & 15);
    int oy0 = blockIdx.x * 32;
#pragma unroll
    for (int j = threadIdx.y; j < 32; j += 8)
        out[(size_t)(oy0 + j) * 512 + sx] = __float2half_rn(tile[threadIdx.x][j]);
}

// ---------------- row softmax over 4096 halves, in place ----------------
__global__ __launch_bounds__(256)
void softmax_h(__half* __restrict__ S) {
    __half* p = S + (size_t)blockIdx.x * NTOK;
    const int t = threadIdx.x;
    uint4 u0 = reinterpret_cast<uint4*>(p)[2 * t];
    uint4 u1 = reinterpret_cast<uint4*>(p)[2 * t + 1];
    float v[16];
    {
        const __half2* h0 = reinterpret_cast<const __half2*>(&u0);
        const __half2* h1 = reinterpret_cast<const __half2*>(&u1);
#pragma unroll
        for (int i = 0; i < 4; i++) {
            float2 f = __half22float2(h0[i]); v[2 * i] = f.x; v[2 * i + 1] = f.y;
            float2 g = __half22float2(h1[i]); v[8 + 2 * i] = g.x; v[9 + 2 * i] = g.y;
        }
    }
    float m = v[0];
#pragma unroll
    for (int i = 1; i < 16; i++) m = fmaxf(m, v[i]);
    __shared__ float red[256];
    red[t] = m; __syncthreads();
    for (int s = 128; s > 0; s >>= 1) { if (t < s) red[t] = fmaxf(red[t], red[t + s]); __syncthreads(); }
    m = red[0]; __syncthreads();
    float sum = 0.f;
#pragma unroll
    for (int i = 0; i < 16; i++) { v[i] = __expf(v[i] - m); sum += v[i]; }
    red[t] = sum; __syncthreads();
    for (int s = 128; s > 0; s >>= 1) { if (t < s) red[t] += red[t + s]; __syncthreads(); }
    const float inv = 1.0f / red[0];
    __half2 h[8];
#pragma unroll
    for (int i = 0; i < 8; i++)
        h[i] = __floats2half2_rn(v[2 * i] * inv, v[2 * i + 1] * inv);
    reinterpret_cast<uint4*>(p)[2 * t]     = *reinterpret_cast<uint4*>(h);
    reinterpret_cast<uint4*>(p)[2 * t + 1] = *reinterpret_cast<uint4*>(h + 4);
}

// ---------------- launch ----------------
extern "C" void kernel_launch(void* const* d_in, const int* in_sizes, int n_in,
                              void* d_out, int out_size) {
    const float* qX  = (const float*)d_in[0];
    const float* kX  = (const float*)d_in[1];
    const float* vX  = (const float*)d_in[2];
    const float* W_Q = (const float*)d_in[3];
    const float* b_Q = (const float*)d_in[4];
    const float* W_K = (const float*)d_in[5];
    const float* b_K = (const float*)d_in[6];
    const float* W_V = (const float*)d_in[7];
    const float* b_V = (const float*)d_in[8];
    float* out = (float*)d_out;

    __half *Q, *K, *Vt, *S, *Wt;
    cudaGetSymbolAddress((void**)&Q,  g_Q);
    cudaGetSymbolAddress((void**)&K,  g_K);
    cudaGetSymbolAddress((void**)&Vt, g_Vt);
    cudaGetSymbolAddress((void**)&S,  g_S);
    cudaGetSymbolAddress((void**)&Wt, g_Wt);

    cudaFuncSetAttribute(gemm_h<true,  1>, cudaFuncAttributeMaxDynamicSharedMemorySize, SMEM_TOT);
    cudaFuncSetAttribute(gemm_h<true,  3>, cudaFuncAttributeMaxDynamicSharedMemorySize, SMEM_TOT);
    cudaFuncSetAttribute(gemm_h<false, 2>, cudaFuncAttributeMaxDynamicSharedMemorySize, SMEM_TOT);
    cudaFuncSetAttribute(gemm_h<false, 0>, cudaFuncAttributeMaxDynamicSharedMemorySize, SMEM_TOT);

    const long long sQKV = (long long)NTOK * DIM;
    const long long sS   = (long long)NTOK * NTOK;
    const size_t nin = (size_t)MTOT * DIM;

    // prepped half inputs live in g_S until scores GEMM overwrites it
    __half* qR = S;
    __half* kR = S + nin;
    __half* vR = S + 2 * nin;

    // 0) prepass inputs + weights
    {
        int n16 = (int)(nin / 16);
        prep_h<<<(n16 + 255) / 256, 256>>>(qX, qR, n16);
        prep_h<<<(n16 + 255) / 256, 256>>>(kX, kR, n16);
        prep_h<<<(n16 + 255) / 256, 256>>>(vX, vR, n16);
        dim3 g(16, 16), b(32, 8);
        transpose512h<<<g, b>>>(W_Q, Wt);
        transpose512h<<<g, b>>>(W_K, Wt + (size_t)DIM * DIM);
        transpose512h<<<g, b>>>(W_V, Wt + 2 * (size_t)DIM * DIM);
    }

    // 1) projections (Q pre-scaled); outputs half + perm16 for next-stage k
    {
        dim3 grid(DIM / BN, MTOT / BM, 1);
        gemm_h<true, 1><<<grid, 256, SMEM_TOT>>>(qR, Wt, b_Q, Q,
            DIM, DIM, DIM, DIM, SM_SCALE, 0, 0, 0);
        gemm_h<true, 1><<<grid, 256, SMEM_TOT>>>(kR, Wt + (size_t)DIM * DIM, b_K, K,
            DIM, DIM, DIM, DIM, 1.0f, 0, 0, 0);
        gemm_h<true, 3><<<grid, 256, SMEM_TOT>>>(vR, Wt + 2 * (size_t)DIM * DIM, b_V, Vt,
            DIM, DIM, DIM, DIM, 1.0f, 0, 0, 0);
    }

    // 2) scores: S[b] = Q[b] @ K[b]^T (scale folded into Q); cols stored tok-perm16
    {
        dim3 grid(NTOK / BN, NTOK / BM, NBATCH);
        gemm_h<false, 2><<<grid, 256, SMEM_TOT>>>(Q, K, nullptr, S,
            NTOK, DIM, DIM, DIM, 1.0f, sQKV, sQKV, sS);
    }

    // 3) softmax (perm-invariant row reduction)
    softmax_h<<<MTOT, 256>>>(S);

    // 4) out[b] = P[b] @ Vt[b]^T (tok perm consistent between P cols and Vt cols)
    {
        dim3 grid(DIM / BN, NTOK / BM, NBATCH);
        gemm_h<false, 0><<<grid, 256, SMEM_TOT>>>(S, Vt, nullptr, out,
            DIM, NTOK, NTOK, NTOK, 1.0f, sS, sQKV, sQKV);
    }
}

// round 8
// speedup vs baseline: 1.0361x; 1.0361x over previous
#include <cuda_runtime.h>
#include <cuda_fp16.h>
#include <cstdint>

#define NBATCH 4
#define NTOK   4096
#define DIM    512
#define MTOT   (NBATCH * NTOK)
#define SM_SCALE 0.044194173824159216f   // 1/sqrt(512)
#define NCOLBLK (NTOK / 128)             // 32 scores column blocks

// ---------------- scratch (half precision) ----------------
__device__ __half g_Q [(size_t)MTOT * DIM];            // 16 MB, cols perm16, pre-scaled
__device__ __half g_K [(size_t)MTOT * DIM];            // 16 MB, cols perm16
__device__ __half g_Vt[(size_t)MTOT * DIM];            // 16 MB, per-batch [dim][tok], tok perm16
__device__ __half g_S [(size_t)NBATCH * NTOK * NTOK];  // 134 MB (hosts prepped inputs pre-scores)
__device__ __half g_Wt[3ULL * DIM * DIM];              // 1.5 MB transposed + perm16
__device__ float  g_part[(size_t)NBATCH * NCOLBLK * NTOK];  // 2 MB partial row sums of exp(S)

// ---------------- helpers ----------------
__device__ __forceinline__ int pos16(int j) {
    return ((j & 6) << 1) | ((j & 8) >> 2) | (j & 1);
}
__device__ __forceinline__ void mma_f16(float* d, const uint32_t* a, const uint32_t* b) {
    asm volatile(
        "mma.sync.aligned.m16n8k16.row.col.f32.f16.f16.f32 "
        "{%0,%1,%2,%3}, {%4,%5,%6,%7}, {%8,%9}, {%0,%1,%2,%3};"
        : "+f"(d[0]), "+f"(d[1]), "+f"(d[2]), "+f"(d[3])
        : "r"(a[0]), "r"(a[1]), "r"(a[2]), "r"(a[3]), "r"(b[0]), "r"(b[1]));
}
__device__ __forceinline__ uint32_t smem_u32(const void* p) {
    uint32_t r;
    asm("{ .reg .u64 t; cvta.to.shared.u64 t, %1; cvt.u32.u64 %0, t; }" : "=r"(r) : "l"(p));
    return r;
}
__device__ __forceinline__ void cpa16(uint32_t dst, const void* src) {
    asm volatile("cp.async.cg.shared.global [%0], [%1], 16;" :: "r"(dst), "l"(src));
}
#define CP_COMMIT() asm volatile("cp.async.commit_group;" ::: "memory")
#define CP_WAIT2()  asm volatile("cp.async.wait_group 2;" ::: "memory")

// FMA-only exp: magic-round split + degree-4 Taylor of 2^f on [-0.5,0.5]; rel err ~4e-5.
__device__ __forceinline__ float fexp(float x) {
    float y = x * 1.4426950408889634f;
    float r = y + 12582912.0f;                         // round-to-nearest integer
    int   i = __float_as_int(r) - 0x4B400000;
    float f = y - (r - 12582912.0f);                   // frac in [-0.5, 0.5]
    float p = 0.0096181291f;
    p = fmaf(p, f, 0.0555041087f);
    p = fmaf(p, f, 0.2402265069f);
    p = fmaf(p, f, 0.6931471806f);
    p = fmaf(p, f, 1.0f);
    return __int_as_float(__float_as_int(p) + (i << 23));
}

// ---------------- tiling (R6 config — measured best) ----------------
#define BM 128
#define BN 128
#define BK 32
#define ROWB 96
#define TILE_BYTES (128 * ROWB)
#define STAGE_BYTES (2 * TILE_BYTES)
#define NSTAGE 3
#define SMEM_MAIN (NSTAGE * STAGE_BYTES)     // 73728
#define SMEM_TOT  (SMEM_MAIN + 1024)         // + partial-sum / invsum scratch

// ---------------- fp16 tensor-core GEMM: C[M,N] = alpha*(A @ B^T + bias) ----------------
// OM: 1 = half out, col perm16 (Q/K proj); 3 = half transposed [dim][tok], tok perm16 (V);
//     2 = scores: exp() fused, half out col perm16, partial row sums -> part;
//     4 = AV: fp32 out, normalized by 1/rowsum from part.
template <bool BIAS, int OM>
__global__ __launch_bounds__(128, 2)
void gemm_h(const __half* __restrict__ Ag, const __half* __restrict__ Bg,
            const float* __restrict__ bias, void* __restrict__ Cg,
            float* __restrict__ part,
            int N, int K, int lda, int ldb, float alpha,
            long long sA, long long sB, long long sC) {
    extern __shared__ char smem[];
    const uint32_t sbase = smem_u32(smem);

    const int t    = threadIdx.x;
    const int lane = t & 31;
    const int w    = t >> 5;
    const int wm   = (w & 1) * 64;
    const int wn   = (w >> 1) * 64;
    const int m0   = blockIdx.y * BM;
    const int n0   = blockIdx.x * BN;
    const int bz   = blockIdx.z;

    const __half* A = Ag + (long long)bz * sA;
    const __half* B = Bg + (long long)bz * sB;

    // AV prologue: reduce partial row sums -> invsum in smem
    float* invs = reinterpret_cast<float*>(smem + SMEM_MAIN);
    if (OM == 4) {
        float s = 0.0f;
        if (t < 128) {
#pragma unroll
            for (int k = 0; k < NCOLBLK; k++)
                s += part[((long long)bz * NCOLBLK + k) * NTOK + m0 + t];
            invs[t] = 1.0f / s;
        }
        __syncthreads();
    }

    // staging: 4 lanes per row (16B each)
    const int rbase = t >> 2;
    const int ch    = t & 3;
    const __half* Arow = A + (long long)m0 * lda + ch * 8;
    const __half* Brow = B + (long long)n0 * ldb + ch * 8;

    auto issue = [&](int c, int buf) {
        const int k0 = c * BK;
        const uint32_t da = sbase + (uint32_t)buf * STAGE_BYTES;
        const uint32_t db = da + TILE_BYTES;
#pragma unroll
        for (int i = 0; i < 4; i++) {
            const int r = rbase + 32 * i;
            cpa16(da + r * ROWB + ch * 16, Arow + (long long)r * lda + k0);
            cpa16(db + r * ROWB + ch * 16, Brow + (long long)r * ldb + k0);
        }
    };

    float acc[4][8][4];
#pragma unroll
    for (int i = 0; i < 4; i++)
#pragma unroll
        for (int j = 0; j < 8; j++)
#pragma unroll
            for (int q = 0; q < 4; q++) acc[i][j][q] = 0.0f;

    const int nchunk = K >> 5;
    issue(0, 0); CP_COMMIT();
    issue(1, 1); CP_COMMIT();
    issue(2, 2); CP_COMMIT();

    const int fr = lane >> 2;
    const int fj = lane & 3;

    for (int c = 0; c < nchunk; c++) {
        const int buf = c % NSTAGE;
        CP_WAIT2();
        __syncthreads();

        const char* As = smem + buf * STAGE_BYTES;
        const char* Bs = As + TILE_BYTES;

#pragma unroll
        for (int ks = 0; ks < 2; ks++) {
            const int off = ks * 32 + 8 * fj;
            uint32_t a[4][4], b[8][2];
#pragma unroll
            for (int ma = 0; ma < 4; ma++) {
                const char* pr = As + (wm + 16 * ma + fr) * ROWB + off;
                uint2 lo = *reinterpret_cast<const uint2*>(pr);
                uint2 hi = *reinterpret_cast<const uint2*>(pr + 8 * ROWB);
                a[ma][0] = lo.x; a[ma][2] = lo.y;
                a[ma][1] = hi.x; a[ma][3] = hi.y;
            }
#pragma unroll
            for (int na = 0; na < 8; na++) {
                uint2 v = *reinterpret_cast<const uint2*>(Bs + (wn + 8 * na + fr) * ROWB + off);
                b[na][0] = v.x; b[na][1] = v.y;
            }
#pragma unroll
            for (int ma = 0; ma < 4; ma++)
#pragma unroll
                for (int na = 0; na < 8; na++)
                    mma_f16(acc[ma][na], a[ma], b[na]);
        }

        __syncthreads();
        if (c + NSTAGE < nchunk) issue(c + NSTAGE, buf);
        CP_COMMIT();
    }

    // ---------------- epilogue ----------------
    const int fp = 2 * fj;
    float rs[4][2];                               // OM2: per-thread row partial sums
#pragma unroll
    for (int i = 0; i < 4; i++) { rs[i][0] = 0.0f; rs[i][1] = 0.0f; }

#pragma unroll
    for (int ma = 0; ma < 4; ma++) {
        const int r0 = m0 + wm + ma * 16 + fr;
#pragma unroll
        for (int na = 0; na < 8; na++) {
            const int col = n0 + wn + na * 8 + fp;   // logical col (even)
            float v0 = acc[ma][na][0], v1 = acc[ma][na][1];
            float v2 = acc[ma][na][2], v3 = acc[ma][na][3];
            if (BIAS) {
                const float b0 = bias[col], b1 = bias[col + 1];
                v0 += b0; v1 += b1; v2 += b0; v3 += b1;
            }
            if (OM == 1 || OM == 3) { v0 *= alpha; v1 *= alpha; v2 *= alpha; v3 *= alpha; }

            if (OM == 2) {
                v0 = fexp(v0); v1 = fexp(v1); v2 = fexp(v2); v3 = fexp(v3);
                rs[ma][0] += v0 + v1;
                rs[ma][1] += v2 + v3;
                const int scol = (col & ~15) | pos16(col & 15);
                __half* o = (__half*)Cg + (long long)bz * sC;
                *reinterpret_cast<__half2*>(o + (long long)r0 * N + scol) =
                    __floats2half2_rn(v0, v1);
                *reinterpret_cast<__half2*>(o + (long long)(r0 + 8) * N + scol) =
                    __floats2half2_rn(v2, v3);
            } else if (OM == 3) {
                const int tokb = (r0 & (NTOK - 1)) & ~15;
                const int tp   = pos16(r0 & 15);
                __half* o = (__half*)Cg + (long long)(r0 >> 12) * ((long long)DIM * NTOK);
                o[(long long)col * NTOK + tokb + tp]           = __float2half_rn(v0);
                o[(long long)(col + 1) * NTOK + tokb + tp]     = __float2half_rn(v1);
                o[(long long)col * NTOK + tokb + tp + 2]       = __float2half_rn(v2);
                o[(long long)(col + 1) * NTOK + tokb + tp + 2] = __float2half_rn(v3);
            } else if (OM == 1) {
                const int scol = (col & ~15) | pos16(col & 15);
                __half* o = (__half*)Cg + (long long)bz * sC;
                *reinterpret_cast<__half2*>(o + (long long)r0 * N + scol) =
                    __floats2half2_rn(v0, v1);
                *reinterpret_cast<__half2*>(o + (long long)(r0 + 8) * N + scol) =
                    __floats2half2_rn(v2, v3);
            } else { // OM == 4: normalized fp32 output
                const float i0 = invs[wm + 16 * ma + fr];
                const float i1 = invs[wm + 16 * ma + fr + 8];
                float* o = (float*)Cg + (long long)bz * sC;
                *reinterpret_cast<float2*>(o + (long long)r0 * N + col) =
                    make_float2(v0 * i0, v1 * i0);
                *reinterpret_cast<float2*>(o + (long long)(r0 + 8) * N + col) =
                    make_float2(v2 * i1, v3 * i1);
            }
        }
    }

    // OM2: reduce row sums across the CTA and emit partials
    if (OM == 2) {
        float (*spart)[2] = reinterpret_cast<float (*)[2]>(smem + SMEM_MAIN);
        const int wgrp = w >> 1;                       // 0: cols 0-63, 1: cols 64-127
        __syncthreads();                               // staging smem no longer needed
#pragma unroll
        for (int ma = 0; ma < 4; ma++) {
            float s0 = rs[ma][0], s1 = rs[ma][1];
            s0 += __shfl_xor_sync(0xFFFFFFFF, s0, 1);
            s0 += __shfl_xor_sync(0xFFFFFFFF, s0, 2);
            s1 += __shfl_xor_sync(0xFFFFFFFF, s1, 1);
            s1 += __shfl_xor_sync(0xFFFFFFFF, s1, 2);
            if (fj == 0) {
                spart[wm + 16 * ma + fr][wgrp]     = s0;
                spart[wm + 16 * ma + fr + 8][wgrp] = s1;
            }
        }
        __syncthreads();
        if (t < 128) {
            const float s = spart[t][0] + spart[t][1];
            part[((long long)bz * NCOLBLK + blockIdx.x) * NTOK + m0 + t] = s;
        }
    }
}

// ---------------- input prepass: fp32 -> half with perm16 ----------------
__global__ __launch_bounds__(256)
void prep_h(const float* __restrict__ in, __half* __restrict__ out, int n16) {
    int i = blockIdx.x * 256 + threadIdx.x;
    if (i >= n16) return;
    const float4* p = reinterpret_cast<const float4*>(in) + 4 * (size_t)i;
    float L[16];
    *reinterpret_cast<float4*>(L)      = p[0];
    *reinterpret_cast<float4*>(L + 4)  = p[1];
    *reinterpret_cast<float4*>(L + 8)  = p[2];
    *reinterpret_cast<float4*>(L + 12) = p[3];
    __half2 h[8];
#pragma unroll
    for (int tt = 0; tt < 4; tt++) {
        h[2 * tt]     = __floats2half2_rn(L[2 * tt],     L[2 * tt + 1]);
        h[2 * tt + 1] = __floats2half2_rn(L[2 * tt + 8], L[2 * tt + 9]);
    }
    uint4* o = reinterpret_cast<uint4*>(out + 16 * (size_t)i);
    o[0] = *reinterpret_cast<uint4*>(h);
    o[1] = *reinterpret_cast<uint4*>(h + 4);
}

// ---------------- 512x512 weight transpose -> half + perm16 on in_dim ----------------
__global__ void transpose512h(const float* __restrict__ in, __half* __restrict__ out) {
    __shared__ float tile[32][33];
    int x = blockIdx.x * 32 + threadIdx.x;
    int y0 = blockIdx.y * 32;
#pragma unroll
    for (int j = threadIdx.y; j < 32; j += 8)
        tile[j][threadIdx.x] = in[(size_t)(y0 + j) * 512 + x];
    __syncthreads();
    int ox = y0 + threadIdx.x;
    int sx = (ox & ~15) | pos16(ox & 15);
    int oy0 = blockIdx.x * 32;
#pragma unroll
    for (int j = threadIdx.y; j < 32; j += 8)
        out[(size_t)(oy0 + j) * 512 + sx] = __float2half_rn(tile[threadIdx.x][j]);
}

// ---------------- launch ----------------
extern "C" void kernel_launch(void* const* d_in, const int* in_sizes, int n_in,
                              void* d_out, int out_size) {
    const float* qX  = (const float*)d_in[0];
    const float* kX  = (const float*)d_in[1];
    const float* vX  = (const float*)d_in[2];
    const float* W_Q = (const float*)d_in[3];
    const float* b_Q = (const float*)d_in[4];
    const float* W_K = (const float*)d_in[5];
    const float* b_K = (const float*)d_in[6];
    const float* W_V = (const float*)d_in[7];
    const float* b_V = (const float*)d_in[8];
    float* out = (float*)d_out;

    __half *Q, *K, *Vt, *S, *Wt;
    float* part;
    cudaGetSymbolAddress((void**)&Q,    g_Q);
    cudaGetSymbolAddress((void**)&K,    g_K);
    cudaGetSymbolAddress((void**)&Vt,   g_Vt);
    cudaGetSymbolAddress((void**)&S,    g_S);
    cudaGetSymbolAddress((void**)&Wt,   g_Wt);
    cudaGetSymbolAddress((void**)&part, g_part);

    cudaFuncSetAttribute(gemm_h<true,  1>, cudaFuncAttributeMaxDynamicSharedMemorySize, SMEM_TOT);
    cudaFuncSetAttribute(gemm_h<true,  3>, cudaFuncAttributeMaxDynamicSharedMemorySize, SMEM_TOT);
    cudaFuncSetAttribute(gemm_h<false, 2>, cudaFuncAttributeMaxDynamicSharedMemorySize, SMEM_TOT);
    cudaFuncSetAttribute(gemm_h<false, 4>, cudaFuncAttributeMaxDynamicSharedMemorySize, SMEM_TOT);

    const long long sQKV = (long long)NTOK * DIM;
    const long long sS   = (long long)NTOK * NTOK;
    const size_t nin = (size_t)MTOT * DIM;

    __half* qR = S;
    __half* kR = S + nin;
    __half* vR = S + 2 * nin;

    // 0) prepass inputs + weights
    {
        int n16 = (int)(nin / 16);
        prep_h<<<(n16 + 255) / 256, 256>>>(qX, qR, n16);
        prep_h<<<(n16 + 255) / 256, 256>>>(kX, kR, n16);
        prep_h<<<(n16 + 255) / 256, 256>>>(vX, vR, n16);
        dim3 g(16, 16), b(32, 8);
        transpose512h<<<g, b>>>(W_Q, Wt);
        transpose512h<<<g, b>>>(W_K, Wt + (size_t)DIM * DIM);
        transpose512h<<<g, b>>>(W_V, Wt + 2 * (size_t)DIM * DIM);
    }

    // 1) projections (Q pre-scaled by 1/sqrt(d))
    {
        dim3 grid(DIM / BN, MTOT / BM, 1);
        gemm_h<true, 1><<<grid, 128, SMEM_TOT>>>(qR, Wt, b_Q, Q, nullptr,
            DIM, DIM, DIM, DIM, SM_SCALE, 0, 0, 0);
        gemm_h<true, 1><<<grid, 128, SMEM_TOT>>>(kR, Wt + (size_t)DIM * DIM, b_K, K, nullptr,
            DIM, DIM, DIM, DIM, 1.0f, 0, 0, 0);
        gemm_h<true, 3><<<grid, 128, SMEM_TOT>>>(vR, Wt + 2 * (size_t)DIM * DIM, b_V, Vt, nullptr,
            DIM, DIM, DIM, DIM, 1.0f, 0, 0, 0);
    }

    // 2) scores + fused exp + partial row sums: S[b] = exp(Q[b] @ K[b]^T)
    {
        dim3 grid(NTOK / BN, NTOK / BM, NBATCH);
        gemm_h<false, 2><<<grid, 128, SMEM_TOT>>>(Q, K, nullptr, S, part,
            NTOK, DIM, DIM, DIM, 1.0f, sQKV, sQKV, sS);
    }

    // 3) out[b] = (E[b] @ Vt[b]^T) / rowsum  — softmax normalization fused
    {
        dim3 grid(DIM / BN, NTOK / BM, NBATCH);
        gemm_h<false, 4><<<grid, 128, SMEM_TOT>>>(S, Vt, nullptr, out, part,
            DIM, NTOK, NTOK, NTOK, 1.0f, sS, sQKV, sQKV);
    }
}